// round 4
// baseline (speedup 1.0000x reference)
#include <cuda_runtime.h>

#define N_TRAJ  256
#define T_LEN   1024
#define K_TYPES 1000
#define D_EMB   64
#define EPS     1e-8f

// emb work: N*T*D = 16,777,216 floats. Bulk is float4 stores at out_emb+3
// (16B-aligned): EMB_BULK4 float4s cover float pos [3, 16777215); head pos
// {0,1,2} and tail pos {16777215} are edge work.
#define EMB_TOTAL    (N_TRAJ * T_LEN * D_EMB)          // 16777216
#define EMB_BULK4    ((EMB_TOTAL - 4) / 4)             // 4194303
#define EMB_HALF     ((EMB_BULK4 + 1) / 2)             // 2097152
#define EMB_BLOCKS   (EMB_HALF / 256)                  // 8192

__device__ int g_reduce_ctr;   // zero-init; reset at end of each launch

// One output float4 at pos = 3 + 4*t4  (d = pos & 63 is ≡ 3 mod 4).
// lo = aligned table[e][d-3 .. d].  hi (= table[.][d+1 .. d+4]) is exactly
// the NEXT lane's lo (row-wrap at d==63 matches the next thread's next-row
// [0..3] load), fetched via shuffle; lane 31 loads hi explicitly.
// All 32 lanes must reach the shuffles; only the store is predicated.
__device__ __forceinline__ void emb_one(int t4, bool store_ok, int lane,
                                        const int* __restrict__ event_types,
                                        const float* __restrict__ type_table,
                                        float* __restrict__ out_emb) {
    const int pos = 3 + 4 * t4;
    const int row = pos >> 6;
    const int d   = pos & (D_EMB - 1);            // 3,7,...,63

    const int e = __ldg(&event_types[row]);
    const float4 lo = __ldg((const float4*)(type_table + e * D_EMB + (d - 3)));

    float hx = __shfl_down_sync(0xffffffffu, lo.x, 1);
    float hy = __shfl_down_sync(0xffffffffu, lo.y, 1);
    float hz = __shfl_down_sync(0xffffffffu, lo.z, 1);

    if (lane == 31 && store_ok) {
        int e2 = e, off = d + 1;
        if (d == D_EMB - 1) {                      // wrap to next row
            e2  = __ldg(&event_types[row + 1]);
            off = 0;
        }
        const float4 hi = __ldg((const float4*)(type_table + e2 * D_EMB + off));
        hx = hi.x; hy = hi.y; hz = hi.z;
    }

    if (store_ok) {
        float4 v;
        v.x = lo.w; v.y = hx; v.z = hy; v.w = hz;
        *reinterpret_cast<float4*>(out_emb + pos) = v;
    }
}

// ---------------------------------------------------------------------------
// Fused kernel:
//   blocks [0, 256)           : per-trajectory reduction; last-done block also
//                               computes the scalar sum (deterministic order).
//   blocks [256, 256+8192)    : embedding gather, 2 float4s per thread,
//                               1 LDG.128 + 3 SHFL + 1 STG.128 per quad.
// ---------------------------------------------------------------------------
__global__ void fused_kernel(const int* __restrict__ event_types,
                             const float* __restrict__ prob_event,
                             const float* __restrict__ intensities,
                             const float* __restrict__ Lambda,
                             const float* __restrict__ input_mask,
                             const float* __restrict__ type_table,
                             float* __restrict__ out,
                             float* __restrict__ out_emb) {
    const int tid = threadIdx.x;

    if (blockIdx.x < N_TRAJ) {
        // ---------------- reduction path ----------------
        const int n = blockIdx.x;
        const int base = n * T_LEN;

        float m[4], inz[4], p[4];
        #pragma unroll
        for (int i = 0; i < 4; i++) {
            const int t = base + tid + i * 256;
            m[i]   = input_mask[t];
            inz[i] = intensities[t];
            const int e = event_types[t];
            p[i] = __ldg(&prob_event[(long long)t * K_TYPES + e]);
        }

        float ev = 0.0f, tm = 0.0f;
        #pragma unroll
        for (int i = 0; i < 4; i++) {
            tm = fmaf(__logf(inz[i] + EPS), m[i], tm);
            ev = fmaf(__logf(p[i]   + EPS), m[i], ev);
        }

        __shared__ float s_ev[256];
        __shared__ float s_tm[256];
        s_ev[tid] = ev;
        s_tm[tid] = tm;
        __syncthreads();

        #pragma unroll
        for (int s = 128; s > 0; s >>= 1) {
            if (tid < s) {
                s_ev[tid] += s_ev[tid + s];
                s_tm[tid] += s_tm[tid + s];
            }
            __syncthreads();
        }

        if (tid == 0) {
            const float tnt = s_tm[0] - Lambda[n];
            out[n]              = tnt + s_ev[0];   // ll_N
            out[N_TRAJ + 1 + n] = tnt;             // time_loglik_NT
        }

        // ----- deterministic fold of the scalar sum into the last block -----
        __threadfence();
        __shared__ int is_last;
        if (tid == 0) {
            const int v = atomicAdd(&g_reduce_ctr, 1);
            is_last = (v == N_TRAJ - 1);
        }
        __syncthreads();
        if (is_last) {
            __threadfence();
            s_ev[tid] = out[tid];
            __syncthreads();
            #pragma unroll
            for (int s = 128; s > 0; s >>= 1) {
                if (tid < s) s_ev[tid] += s_ev[tid + s];
                __syncthreads();
            }
            if (tid == 0) {
                out[N_TRAJ] = s_ev[0];              // time_loglik
                g_reduce_ctr = 0;                   // reset for graph replay
            }
        }
        return;
    }

    // ---------------- embedding path ----------------
    const int lane = tid & 31;
    const int i = (blockIdx.x - N_TRAJ) * 256 + tid;   // i < EMB_HALF

    emb_one(i, true, lane, event_types, type_table, out_emb);
    // second batch: t4 in [EMB_HALF, 2*EMB_HALF); last t4 (== EMB_BULK4) only
    // loads (in-bounds), store predicated off; warp stays converged for shfl.
    const int t4b = i + EMB_HALF;
    emb_one(t4b, t4b < EMB_BULK4, lane, event_types, type_table, out_emb);

    if (blockIdx.x == N_TRAJ && tid == 0) {
        // head pos 0,1,2 (row 0) and tail pos EMB_TOTAL-1
        const int e0 = __ldg(&event_types[0]);
        out_emb[0] = __ldg(&type_table[e0 * D_EMB + 0]);
        out_emb[1] = __ldg(&type_table[e0 * D_EMB + 1]);
        out_emb[2] = __ldg(&type_table[e0 * D_EMB + 2]);
        const int lrow = (EMB_TOTAL - 1) >> 6;
        const int el = __ldg(&event_types[lrow]);
        out_emb[EMB_TOTAL - 1] = __ldg(&type_table[el * D_EMB + (D_EMB - 1)]);
    }
}

extern "C" void kernel_launch(void* const* d_in, const int* in_sizes, int n_in,
                              void* d_out, int out_size) {
    const int*   event_types = (const int*)  d_in[0];   // (N, T) int32
    const float* prob_event  = (const float*)d_in[1];   // (N, T, K)
    const float* intensities = (const float*)d_in[2];   // (N, T)
    const float* Lambda      = (const float*)d_in[3];   // (N,)
    const float* input_mask  = (const float*)d_in[4];   // (N, T)
    const float* type_table  = (const float*)d_in[5];   // (K, D)

    float* out = (float*)d_out;
    // Layout: [ll_N (256)] [time_loglik (1)] [time_loglik_NT (256)] [type_emb]
    float* out_emb = out + (N_TRAJ + 1 + N_TRAJ);

    fused_kernel<<<N_TRAJ + EMB_BLOCKS, 256>>>(event_types, prob_event,
                                               intensities, Lambda, input_mask,
                                               type_table, out, out_emb);
}

// round 5
// speedup vs baseline: 1.0980x; 1.0980x over previous
#include <cuda_runtime.h>

#define N_TRAJ  256
#define T_LEN   1024
#define K_TYPES 1000
#define D_EMB   64
#define EPS     1e-8f

#define N_ROWS      (N_TRAJ * T_LEN)                   // 262144
#define EMB_TOTAL   (N_ROWS * D_EMB)                   // 16777216
#define EMB_BULK4   ((EMB_TOTAL - 4) / 4)              // 4194303 quads at pos 3+4q
#define QUADS_PER_BLOCK 512                            // 256 thr x 2 quads = 32 rows
#define EMB_BLOCKS  ((EMB_BULK4 + QUADS_PER_BLOCK - 1) / QUADS_PER_BLOCK)  // 8192

__device__ int g_reduce_ctr;   // zero-init; reset at end of each launch

// ---------------------------------------------------------------------------
// Fused kernel:
//   blocks [0, 256)          : per-trajectory reduction; last-done block also
//                              computes the scalar sum (deterministic order).
//   blocks [256, 256+8192)   : embedding gather. Each block owns 32 rows;
//                              indices staged in smem; 2 quads/thread with
//                              all 4 table LDG.128s issued before stores;
//                              streaming (evict-first) output stores.
// ---------------------------------------------------------------------------
__global__ void fused_kernel(const int* __restrict__ event_types,
                             const float* __restrict__ prob_event,
                             const float* __restrict__ intensities,
                             const float* __restrict__ Lambda,
                             const float* __restrict__ input_mask,
                             const float* __restrict__ type_table,
                             float* __restrict__ out,
                             float* __restrict__ out_emb) {
    const int tid = threadIdx.x;

    if (blockIdx.x < N_TRAJ) {
        // ---------------- reduction path ----------------
        const int n = blockIdx.x;
        const int base = n * T_LEN;

        float m[4], inz[4], p[4];
        #pragma unroll
        for (int i = 0; i < 4; i++) {
            const int t = base + tid + i * 256;
            m[i]   = input_mask[t];
            inz[i] = intensities[t];
            const int e = event_types[t];
            // use-once random gather: evict-first to protect table in L2
            p[i] = __ldcs(&prob_event[(long long)t * K_TYPES + e]);
        }

        float ev = 0.0f, tm = 0.0f;
        #pragma unroll
        for (int i = 0; i < 4; i++) {
            tm = fmaf(__logf(inz[i] + EPS), m[i], tm);
            ev = fmaf(__logf(p[i]   + EPS), m[i], ev);
        }

        __shared__ float s_ev[256];
        __shared__ float s_tm[256];
        s_ev[tid] = ev;
        s_tm[tid] = tm;
        __syncthreads();

        #pragma unroll
        for (int s = 128; s > 0; s >>= 1) {
            if (tid < s) {
                s_ev[tid] += s_ev[tid + s];
                s_tm[tid] += s_tm[tid + s];
            }
            __syncthreads();
        }

        if (tid == 0) {
            const float tnt = s_tm[0] - Lambda[n];
            out[n]              = tnt + s_ev[0];   // ll_N
            out[N_TRAJ + 1 + n] = tnt;             // time_loglik_NT
        }

        // ----- deterministic fold of the scalar sum into the last block -----
        __threadfence();
        __shared__ int is_last;
        if (tid == 0) {
            const int v = atomicAdd(&g_reduce_ctr, 1);
            is_last = (v == N_TRAJ - 1);
        }
        __syncthreads();
        if (is_last) {
            __threadfence();
            s_ev[tid] = out[tid];
            __syncthreads();
            #pragma unroll
            for (int s = 128; s > 0; s >>= 1) {
                if (tid < s) s_ev[tid] += s_ev[tid + s];
                __syncthreads();
            }
            if (tid == 0) {
                out[N_TRAJ] = s_ev[0];              // time_loglik
                g_reduce_ctr = 0;                   // reset for graph replay
            }
        }
        return;
    }

    // ---------------- embedding path ----------------
    const int b = blockIdx.x - N_TRAJ;                 // 0 .. 8191

    // Stage the 33 event indices this block needs (rows 32b .. 32b+32).
    __shared__ int s_idx[33];
    if (tid < 33) {
        const int r = 32 * b + tid;
        s_idx[tid] = (r < N_ROWS) ? event_types[r] : 0;
    }
    __syncthreads();

    const int q0 = b * QUADS_PER_BLOCK + tid;          // quad ids
    const int q1 = q0 + 256;
    const bool ok1 = (q1 < EMB_BULK4);                 // only last block's tail fails

    // quad 0 geometry
    const int pos0  = 3 + 4 * q0;
    const int lrow0 = (pos0 >> 6) - 32 * b;            // 0..15
    const int d0    = pos0 & (D_EMB - 1);              // 3,7,...,63
    // quad 1 geometry
    const int pos1  = 3 + 4 * q1;
    const int lrow1 = (pos1 >> 6) - 32 * b;            // 16..31
    const int d1    = pos1 & (D_EMB - 1);

    const int e0  = s_idx[lrow0];
    const int e0b = (d0 == D_EMB - 1) ? s_idx[lrow0 + 1] : e0;
    const int o0  = (d0 == D_EMB - 1) ? 0 : d0 + 1;

    const int e1  = s_idx[lrow1];
    const int e1b = (d1 == D_EMB - 1) ? s_idx[lrow1 + 1] : e1;
    const int o1  = (d1 == D_EMB - 1) ? 0 : d1 + 1;

    // Issue all 4 table loads before any store (MLP=4).
    const float4 lo0 = __ldg((const float4*)(type_table + e0  * D_EMB + (d0 - 3)));
    const float4 hi0 = __ldg((const float4*)(type_table + e0b * D_EMB + o0));
    float4 lo1, hi1;
    if (ok1) {
        lo1 = __ldg((const float4*)(type_table + e1  * D_EMB + (d1 - 3)));
        hi1 = __ldg((const float4*)(type_table + e1b * D_EMB + o1));
    }

    float4 v0;
    v0.x = lo0.w; v0.y = hi0.x; v0.z = hi0.y; v0.w = hi0.z;
    __stcs(reinterpret_cast<float4*>(out_emb + pos0), v0);

    if (ok1) {
        float4 v1;
        v1.x = lo1.w; v1.y = hi1.x; v1.z = hi1.y; v1.w = hi1.z;
        __stcs(reinterpret_cast<float4*>(out_emb + pos1), v1);
    }

    if (b == 0 && tid == 0) {
        // head pos 0,1,2 (row 0) and tail pos EMB_TOTAL-1
        const int eh = s_idx[0];
        out_emb[0] = __ldg(&type_table[eh * D_EMB + 0]);
        out_emb[1] = __ldg(&type_table[eh * D_EMB + 1]);
        out_emb[2] = __ldg(&type_table[eh * D_EMB + 2]);
        const int lrow = (EMB_TOTAL - 1) >> 6;
        const int el = __ldg(&event_types[lrow]);
        out_emb[EMB_TOTAL - 1] = __ldg(&type_table[el * D_EMB + (D_EMB - 1)]);
    }
}

extern "C" void kernel_launch(void* const* d_in, const int* in_sizes, int n_in,
                              void* d_out, int out_size) {
    const int*   event_types = (const int*)  d_in[0];   // (N, T) int32
    const float* prob_event  = (const float*)d_in[1];   // (N, T, K)
    const float* intensities = (const float*)d_in[2];   // (N, T)
    const float* Lambda      = (const float*)d_in[3];   // (N,)
    const float* input_mask  = (const float*)d_in[4];   // (N, T)
    const float* type_table  = (const float*)d_in[5];   // (K, D)

    float* out = (float*)d_out;
    // Layout: [ll_N (256)] [time_loglik (1)] [time_loglik_NT (256)] [type_emb]
    float* out_emb = out + (N_TRAJ + 1 + N_TRAJ);

    fused_kernel<<<N_TRAJ + EMB_BLOCKS, 256>>>(event_types, prob_event,
                                               intensities, Lambda, input_mask,
                                               type_table, out, out_emb);
}

// round 6
// speedup vs baseline: 1.1357x; 1.0343x over previous
#include <cuda_runtime.h>

#define N_TRAJ  256
#define T_LEN   1024
#define K_TYPES 1000
#define D_EMB   64
#define EPS     1e-8f

#define N_ROWS      (N_TRAJ * T_LEN)                   // 262144
#define EMB_TOTAL   (N_ROWS * D_EMB)                   // 16777216
#define EMB_BULK4   ((EMB_TOTAL - 4) / 4)              // 4194303 quads at pos 3+4q
#define QPT         4                                  // quads per thread
#define QUADS_PER_BLOCK (256 * QPT)                    // 1024 quads = 64 rows
#define EMB_BLOCKS  ((EMB_BULK4 + QUADS_PER_BLOCK - 1) / QUADS_PER_BLOCK)  // 4096

__device__ int g_reduce_ctr;   // zero-init; reset at end of each launch

// ---------------------------------------------------------------------------
// Fused kernel:
//   blocks [0, 256)          : per-trajectory reduction; last-done block also
//                              computes the scalar sum (deterministic order).
//   blocks [256, 256+4096)   : embedding gather. Each block owns 64 rows;
//                              indices staged in smem; 4 quads/thread with
//                              ALL 8 table LDG.128s issued before any store;
//                              streaming (evict-first) output stores.
// ---------------------------------------------------------------------------
__global__ void fused_kernel(const int* __restrict__ event_types,
                             const float* __restrict__ prob_event,
                             const float* __restrict__ intensities,
                             const float* __restrict__ Lambda,
                             const float* __restrict__ input_mask,
                             const float* __restrict__ type_table,
                             float* __restrict__ out,
                             float* __restrict__ out_emb) {
    const int tid = threadIdx.x;

    if (blockIdx.x < N_TRAJ) {
        // ---------------- reduction path ----------------
        const int n = blockIdx.x;
        const int base = n * T_LEN;

        float m[4], inz[4], p[4];
        #pragma unroll
        for (int i = 0; i < 4; i++) {
            const int t = base + tid + i * 256;
            m[i]   = input_mask[t];
            inz[i] = intensities[t];
            const int e = event_types[t];
            // use-once random gather: streaming to protect table in L2
            p[i] = __ldcs(&prob_event[(long long)t * K_TYPES + e]);
        }

        float ev = 0.0f, tm = 0.0f;
        #pragma unroll
        for (int i = 0; i < 4; i++) {
            tm = fmaf(__logf(inz[i] + EPS), m[i], tm);
            ev = fmaf(__logf(p[i]   + EPS), m[i], ev);
        }

        __shared__ float s_ev[256];
        __shared__ float s_tm[256];
        s_ev[tid] = ev;
        s_tm[tid] = tm;
        __syncthreads();

        #pragma unroll
        for (int s = 128; s > 0; s >>= 1) {
            if (tid < s) {
                s_ev[tid] += s_ev[tid + s];
                s_tm[tid] += s_tm[tid + s];
            }
            __syncthreads();
        }

        if (tid == 0) {
            const float tnt = s_tm[0] - Lambda[n];
            out[n]              = tnt + s_ev[0];   // ll_N
            out[N_TRAJ + 1 + n] = tnt;             // time_loglik_NT
        }

        // ----- deterministic fold of the scalar sum into the last block -----
        __threadfence();
        __shared__ int is_last;
        if (tid == 0) {
            const int v = atomicAdd(&g_reduce_ctr, 1);
            is_last = (v == N_TRAJ - 1);
        }
        __syncthreads();
        if (is_last) {
            __threadfence();
            s_ev[tid] = out[tid];
            __syncthreads();
            #pragma unroll
            for (int s = 128; s > 0; s >>= 1) {
                if (tid < s) s_ev[tid] += s_ev[tid + s];
                __syncthreads();
            }
            if (tid == 0) {
                out[N_TRAJ] = s_ev[0];              // time_loglik
                g_reduce_ctr = 0;                   // reset for graph replay
            }
        }
        return;
    }

    // ---------------- embedding path ----------------
    const int b = blockIdx.x - N_TRAJ;                 // 0 .. 4095

    // Stage the 65 event indices this block needs (rows 64b .. 64b+64).
    __shared__ int s_idx[65];
    if (tid < 65) {
        const int r = 64 * b + tid;
        s_idx[tid] = (r < N_ROWS) ? event_types[r] : 0;
    }
    __syncthreads();

    const int qbase = b * QUADS_PER_BLOCK + tid;

    int    pos[QPT];
    bool   ok[QPT];
    float4 lo[QPT], hi[QPT];

    // Phase 1: address math + issue all 8 independent LDG.128s.
    #pragma unroll
    for (int k = 0; k < QPT; k++) {
        const int q = qbase + k * 256;
        ok[k]  = (q < EMB_BULK4);                  // only very last quad fails
        pos[k] = 3 + 4 * q;
        const int lrow = (pos[k] >> 6) - 64 * b;   // 0..63
        const int d    = pos[k] & (D_EMB - 1);     // 3,7,...,63

        const int e  = s_idx[lrow];
        const int eb = (d == D_EMB - 1) ? s_idx[lrow + 1] : e;
        const int o  = (d == D_EMB - 1) ? 0 : d + 1;

        if (ok[k]) {
            lo[k] = __ldg((const float4*)(type_table + e  * D_EMB + (d - 3)));
            hi[k] = __ldg((const float4*)(type_table + eb * D_EMB + o));
        }
    }

    // Phase 2: recombine + streaming stores.
    #pragma unroll
    for (int k = 0; k < QPT; k++) {
        if (ok[k]) {
            float4 v;
            v.x = lo[k].w; v.y = hi[k].x; v.z = hi[k].y; v.w = hi[k].z;
            __stcs(reinterpret_cast<float4*>(out_emb + pos[k]), v);
        }
    }

    if (b == 0 && tid == 0) {
        // head pos 0,1,2 (row 0) and tail pos EMB_TOTAL-1
        const int eh = s_idx[0];
        out_emb[0] = __ldg(&type_table[eh * D_EMB + 0]);
        out_emb[1] = __ldg(&type_table[eh * D_EMB + 1]);
        out_emb[2] = __ldg(&type_table[eh * D_EMB + 2]);
        const int lrow = (EMB_TOTAL - 1) >> 6;
        const int el = __ldg(&event_types[lrow]);
        out_emb[EMB_TOTAL - 1] = __ldg(&type_table[el * D_EMB + (D_EMB - 1)]);
    }
}

extern "C" void kernel_launch(void* const* d_in, const int* in_sizes, int n_in,
                              void* d_out, int out_size) {
    const int*   event_types = (const int*)  d_in[0];   // (N, T) int32
    const float* prob_event  = (const float*)d_in[1];   // (N, T, K)
    const float* intensities = (const float*)d_in[2];   // (N, T)
    const float* Lambda      = (const float*)d_in[3];   // (N,)
    const float* input_mask  = (const float*)d_in[4];   // (N, T)
    const float* type_table  = (const float*)d_in[5];   // (K, D)

    float* out = (float*)d_out;
    // Layout: [ll_N (256)] [time_loglik (1)] [time_loglik_NT (256)] [type_emb]
    float* out_emb = out + (N_TRAJ + 1 + N_TRAJ);

    fused_kernel<<<N_TRAJ + EMB_BLOCKS, 256>>>(event_types, prob_event,
                                               intensities, Lambda, input_mask,
                                               type_table, out, out_emb);
}